// round 6
// baseline (speedup 1.0000x reference)
#include <cuda_runtime.h>

#define Vdim   96
#define Kdim   20
#define Bdim   256
#define Ddim   1024
#define NIJ    9
#define GROUPS 144      // 3*3*4*2*2
#define VK     1920     // Vdim*Kdim

// mega kernel geometry
#define BPB    64                  // b's per yphi block
#define SPLITS (Bdim / BPB)        // 4
#define NPHI   (GROUPS * SPLITS)   // 576 yphi-role blocks
#define DCHUNK 20                  // d's per Y block
#define NYB    52                  // ceil(1024/20)
#define NY     (NIJ * NYB)         // 468 Y-role blocks
#define NBLK   (NPHI + NY)         // 1044
#define TMEGA  480                 // threads

// ---- scratch (static device globals — no runtime allocation) ----
__device__ float        g_ytr[NIJ * Ddim];   // sum over (e,n,c,v) of Y -> [ij][d]
__device__ float        g_eT0[VK];           // exp(_T0)
__device__ float        g_lt[VK];            // sigmoid(_t)
__device__ float        g_lr[VK];            // sigmoid(_r)
__device__ float        g_invZ[NIJ * Kdim];  // 1 / sum_v eT0*wt*wr
__device__ float        g_lq[NIJ * Kdim];    // log qt_i + log qr_j per (ij,k)
__device__ float        g_L3[16 * Kdim];     // log pe + log pn + log pc per (enc,k)
__device__ float        g_Wb[NIJ * Bdim];    // sum over (enc,v,k) of yphi -> [ij][b]
__device__ double       g_loss;
__device__ unsigned int g_count;

// ---------------------------------------------------------------------------
// Kernel 1: ALL prep in one block — elementwise tables, Z, log tables, zeroing
// ---------------------------------------------------------------------------
__global__ __launch_bounds__(1024) void k_prep(
    const float* __restrict__ T0p, const float* __restrict__ tp,
    const float* __restrict__ rp,  const float* __restrict__ ep,
    const float* __restrict__ enp, const float* __restrict__ ecp)
{
    __shared__ float se[VK], st[VK], sr[VK];
    __shared__ float scolsum[Kdim];
    __shared__ float sZraw[NIJ * Kdim];
    int t = threadIdx.x, lane = t & 31, w = t >> 5;

    // zero accumulators
    for (int i = t; i < NIJ * Bdim; i += 1024) g_Wb[i] = 0.f;
    if (t == 0) { g_loss = 0.0; g_count = 0u; }

    // elementwise tables (smem + global copies for the mega kernel)
    for (int i = t; i < VK; i += 1024) {
        float e  = __expf(T0p[i]);
        float lt = 1.f / (1.f + __expf(-tp[i]));
        float lr = 1.f / (1.f + __expf(-rp[i]));
        se[i] = e;  st[i] = lt; sr[i] = lr;
        g_eT0[i] = e; g_lt[i] = lt; g_lr[i] = lr;
    }
    __syncthreads();

    // column sums of eT0 over V (warp per column)
    if (w < Kdim) {
        float s = 0.f;
        for (int v = lane; v < Vdim; v += 32) s += se[v * Kdim + w];
#pragma unroll
        for (int off = 16; off; off >>= 1) s += __shfl_down_sync(0xffffffffu, s, off);
        if (lane == 0) scolsum[w] = s;
    }
    // raw Z[ij][k] (warp per output)
    for (int o = w; o < NIJ * Kdim; o += 32) {
        int ij = o / Kdim, k = o - ij * Kdim, i = ij / 3, j = ij % 3;
        float s = 0.f;
        for (int v = lane; v < Vdim; v += 32) {
            int r = v * Kdim + k;
            float wt = (i == 0) ? st[r] : (i == 1) ? 1.f - st[r] : 1.f;
            float wr = (j == 0) ? sr[r] : (j == 1) ? 1.f - sr[r] : 1.f;
            s += se[r] * wt * wr;
        }
#pragma unroll
        for (int off = 16; off; off >>= 1) s += __shfl_down_sync(0xffffffffu, s, off);
        if (lane == 0) sZraw[o] = s;
    }
    __syncthreads();

    if (t < NIJ * Kdim) g_invZ[t] = 1.f / sZraw[t];

    if (t < Kdim) {
        float inv = 1.f / scolsum[t];
        float pt = sZraw[2 * Kdim + t] * inv;   // ij=(0,2): wt=lt, wr=1
        float pr = sZraw[6 * Kdim + t] * inv;   // ij=(2,0): wt=1, wr=lr
        float lqt[3] = { __logf(pt), __logf(1.f - pt), 0.f };
        float lqr[3] = { __logf(pr), __logf(1.f - pr), 0.f };
        for (int ij = 0; ij < NIJ; ++ij)
            g_lq[ij * Kdim + t] = lqt[ij / 3] + lqr[ij % 3];

        float lpe[4], lpn[2], lpc[2]; float s, l;
        s = 0.f; for (int e = 0; e < 4; ++e) s += __expf(ep[e * Kdim + t]);
        l = __logf(s);
        for (int e = 0; e < 4; ++e) lpe[e] = ep[e * Kdim + t] - l;
        s = 0.f; for (int n = 0; n < 2; ++n) s += __expf(enp[n * Kdim + t]);
        l = __logf(s);
        for (int n = 0; n < 2; ++n) lpn[n] = enp[n * Kdim + t] - l;
        s = 0.f; for (int c = 0; c < 2; ++c) s += __expf(ecp[c * Kdim + t]);
        l = __logf(s);
        for (int c = 0; c < 2; ++c) lpc[c] = ecp[c * Kdim + t] - l;
        for (int enc = 0; enc < 16; ++enc)
            g_L3[enc * Kdim + t] = lpe[enc >> 2] + lpn[(enc >> 1) & 1] + lpc[enc & 1];
    }
}

// ---------------------------------------------------------------------------
// Kernel 2 (MEGA): streams yphi (283MB) + Y (56.6MB) in one wave; the last
// block to finish runs the finisher (missing-rate logs + Wb dot + scale).
// ---------------------------------------------------------------------------
__global__ __launch_bounds__(TMEGA) void k_mega(
    const float* __restrict__ yphi, const float* __restrict__ Yv,
    const int* __restrict__ index, float* __restrict__ out)
{
    __shared__ float  sL3[Kdim];
    __shared__ float  sinvZ[Kdim];
    __shared__ float  slq[Kdim];
    __shared__ float  swb[BPB * 16];          // [b][warp], 15 warps pad 16
    __shared__ double sred[TMEGA / 32];
    __shared__ float  sY[TMEGA];
    __shared__ double sfin[256];
    __shared__ int    sDone;

    int blk = blockIdx.x, t = threadIdx.x;
    int lane = t & 31, w = t >> 5;

    if (blk < NPHI) {
        int group  = blk / SPLITS;             // ij*16 + enc
        int bsplit = blk - group * SPLITS;
        int ij = group >> 4, enc = group & 15;
        int i = ij / 3, j = ij % 3;

        if (t < Kdim) {
            sL3[t]   = g_L3[enc * Kdim + t];
            sinvZ[t] = g_invZ[ij * Kdim + t];
            slq[t]   = g_lq[ij * Kdim + t];
        }
        __syncthreads();

        // per-thread weights: wv = log(T) + lq(ij) + L3(enc), computed in-place
        float4 e4  = *(const float4*)(g_eT0 + 4 * t);
        float4 lt4 = *(const float4*)(g_lt  + 4 * t);
        float4 lr4 = *(const float4*)(g_lr  + 4 * t);
        int kb = (4 * t) % Kdim;               // 4|20: never wraps within a float4
        float4 wt4, wr4;
        wt4.x = (i == 0) ? lt4.x : (i == 1) ? 1.f - lt4.x : 1.f;
        wt4.y = (i == 0) ? lt4.y : (i == 1) ? 1.f - lt4.y : 1.f;
        wt4.z = (i == 0) ? lt4.z : (i == 1) ? 1.f - lt4.z : 1.f;
        wt4.w = (i == 0) ? lt4.w : (i == 1) ? 1.f - lt4.w : 1.f;
        wr4.x = (j == 0) ? lr4.x : (j == 1) ? 1.f - lr4.x : 1.f;
        wr4.y = (j == 0) ? lr4.y : (j == 1) ? 1.f - lr4.y : 1.f;
        wr4.z = (j == 0) ? lr4.z : (j == 1) ? 1.f - lr4.z : 1.f;
        wr4.w = (j == 0) ? lr4.w : (j == 1) ? 1.f - lr4.w : 1.f;
        float4 wv;
        wv.x = __logf(e4.x * wt4.x * wr4.x * sinvZ[kb])     + slq[kb]     + sL3[kb];
        wv.y = __logf(e4.y * wt4.y * wr4.y * sinvZ[kb + 1]) + slq[kb + 1] + sL3[kb + 1];
        wv.z = __logf(e4.z * wt4.z * wr4.z * sinvZ[kb + 2]) + slq[kb + 2] + sL3[kb + 2];
        wv.w = __logf(e4.w * wt4.w * wr4.w * sinvZ[kb + 3]) + slq[kb + 3] + sL3[kb + 3];

        const float4* p = (const float4*)(yphi + (size_t)group * (Bdim * VK)
                                               + (size_t)bsplit * BPB * VK) + t;
        float acc = 0.f;
#pragma unroll 8
        for (int b = 0; b < BPB; ++b) {
            float4 x = p[(size_t)b * (VK / 4)];
            acc += x.x * wv.x; acc += x.y * wv.y;
            acc += x.z * wv.z; acc += x.w * wv.w;
            float s = (x.x + x.y) + (x.z + x.w);
#pragma unroll
            for (int off = 16; off; off >>= 1) s += __shfl_down_sync(0xffffffffu, s, off);
            if (lane == 0) swb[b * 16 + w] = s;
        }
        __syncthreads();
        if (t < BPB) {
            float s = 0.f;
#pragma unroll
            for (int w2 = 0; w2 < TMEGA / 32; ++w2) s += swb[t * 16 + w2];
            atomicAdd(&g_Wb[ij * Bdim + bsplit * BPB + t], s);
        }
#pragma unroll
        for (int off = 16; off; off >>= 1) acc += __shfl_down_sync(0xffffffffu, acc, off);
        if (lane == 0) sred[w] = (double)acc;
        __syncthreads();
        if (t == 0) {
            double s = 0.0;
#pragma unroll
            for (int w2 = 0; w2 < TMEGA / 32; ++w2) s += sred[w2];
            atomicAdd(&g_loss, s);
        }
    } else {
        // ---- Y reduction role ----
        int yb    = blk - NPHI;
        int ij    = yb / NYB;
        int chunk = yb - ij * NYB;
        int d0 = chunk * DCHUNK;
        int dl = t / 24, vq = t - dl * 24;     // 20 d's x 24 float4
        int d  = d0 + dl;
        float s = 0.f;
        if (d < Ddim) {
            const float4* q = (const float4*)Yv
                + (size_t)ij * (16 * Ddim * 24) + (size_t)d * 24 + vq;
#pragma unroll
            for (int enc = 0; enc < 16; ++enc) {
                float4 x = q[(size_t)enc * (Ddim * 24)];
                s += (x.x + x.y) + (x.z + x.w);
            }
        }
        sY[t] = s;
        __syncthreads();
        if (t < DCHUNK && d0 + t < Ddim) {
            float r = 0.f;
#pragma unroll
            for (int v = 0; v < 24; ++v) r += sY[t * 24 + v];
            g_ytr[ij * Ddim + d0 + t] = r;
        }
    }

    // ---- last-block finisher ----
    __threadfence();
    if (t == 0) {
        unsigned int v = atomicAdd(&g_count, 1u);
        sDone = (v == NBLK - 1) ? 1 : 0;
    }
    __syncthreads();
    if (!sDone) return;

    if (t < 256) {
        int d = index[t];
        float y[9];
#pragma unroll
        for (int ij = 0; ij < 9; ++ij) y[ij] = g_ytr[ij * Ddim + d];
        float tot = ((y[0] + y[1]) + (y[2] + y[3]))
                  + ((y[4] + y[5]) + (y[6] + y[7])) + y[8];
        float inv = 1.f / tot;
        float lmr[4];
        lmr[0] = __logf((y[0] + y[1] + y[3] + y[4]) * inv);  // m00
        lmr[1] = __logf((y[2] + y[5]) * inv);                // m01
        lmr[2] = __logf((y[6] + y[7]) * inv);                // m10
        lmr[3] = __logf(y[8] * inv);                         // m11
        double acc = 0.0;
#pragma unroll
        for (int ij = 0; ij < 9; ++ij) {
            int i = ij / 3, j = ij % 3;
            int sel = ((i == 2) ? 2 : 0) + ((j == 2) ? 1 : 0);
            acc += (double)g_Wb[ij * Bdim + t] * (double)lmr[sel];
        }
        sfin[t] = acc;
    }
    __syncthreads();
    for (int off = 128; off; off >>= 1) {
        if (t < off) sfin[t] += sfin[t + off];
        __syncthreads();
    }
    if (t == 0) out[0] = (float)(-(g_loss + sfin[0]) / (double)VK);
}

// ---------------------------------------------------------------------------
extern "C" void kernel_launch(void* const* d_in, const int* in_sizes, int n_in,
                              void* d_out, int out_size) {
    (void)in_sizes; (void)n_in; (void)out_size;
    const float* yphi = (const float*)d_in[0];
    const float* Yv   = (const float*)d_in[1];
    const float* T0p  = (const float*)d_in[2];
    const float* tp   = (const float*)d_in[3];
    const float* rp   = (const float*)d_in[4];
    const float* ep   = (const float*)d_in[5];
    const float* enp  = (const float*)d_in[6];
    const float* ecp  = (const float*)d_in[7];
    const int*   idx  = (const int*)d_in[8];
    float* out = (float*)d_out;

    k_prep<<<1, 1024>>>(T0p, tp, rp, ep, enp, ecp);
    k_mega<<<NBLK, TMEGA>>>(yphi, Yv, idx, out);
}